// round 10
// baseline (speedup 1.0000x reference)
#include <cuda_runtime.h>
#include <math.h>
#include <stdint.h>

#define BATCH   4
#define SEQ     2048
#define DMODEL  512
#define NHEAD   8
#define HDIM    64
#define ROWS    (BATCH * SEQ)        /* 8192 */
#define QKVN    (3 * DMODEL)         /* 1536 */

// Scratch (allocation-free rule: device globals)
__device__ float g_qkv[(size_t)ROWS * QKVN];     // [8192, 1536] tf32 bits
__device__ float g_att[(size_t)ROWS * DMODEL];   // [8192, 512] fp32

__device__ __forceinline__ uint32_t f2tf(float x) {
    uint32_t r;
    asm("cvt.rna.tf32.f32 %0, %1;" : "=r"(r) : "f"(x));
    return r;
}

__device__ __forceinline__ void mma_tf32(float c[4], const uint32_t a[4],
                                         uint32_t b0, uint32_t b1) {
    asm volatile(
        "mma.sync.aligned.m16n8k8.row.col.f32.tf32.tf32.f32 "
        "{%0,%1,%2,%3}, {%4,%5,%6,%7}, {%8,%9}, {%0,%1,%2,%3};"
        : "+f"(c[0]), "+f"(c[1]), "+f"(c[2]), "+f"(c[3])
        : "r"(a[0]), "r"(a[1]), "r"(a[2]), "r"(a[3]), "r"(b0), "r"(b1));
}

__device__ __forceinline__ void cp_async16(uint32_t smem_dst, const void* gsrc) {
    asm volatile("cp.async.cg.shared.global [%0], [%1], 16;"
                 :: "r"(smem_dst), "l"(gsrc) : "memory");
}
__device__ __forceinline__ void cp_async_commit() {
    asm volatile("cp.async.commit_group;" ::: "memory");
}
__device__ __forceinline__ void cp_async_wait1() {
    asm volatile("cp.async.wait_group 1;" ::: "memory");
}

// ---------------------------------------------------------------------------
// TF32 tensor-core GEMM, 2-stage cp.async pipeline (unchanged from R9).
// ---------------------------------------------------------------------------
#define GBM 128
#define GBN 128
#define GBK 16
#define APAD 20    /* As row stride (words) */
#define BPAD 136   /* Bs row stride (words) */
#define AW (GBM * APAD)
#define BW (GBK * BPAD)

__global__ __launch_bounds__(256)
void tf32_gemm_kernel(const float* __restrict__ A, const float* __restrict__ B,
                      float* __restrict__ C, int M, int N, int K, int cvt_out) {
    __shared__ float As[2][AW];   // [m][k] raw fp32
    __shared__ float Bs[2][BW];   // [k][n] raw fp32

    const int tid  = threadIdx.x;
    const int warp = tid >> 5;
    const int lane = tid & 31;
    const int g = lane >> 2;
    const int c = lane & 3;
    const int wm = warp >> 2;     // 0..1
    const int wn = warp & 3;      // 0..3

    const int arow = tid >> 1, acol = (tid & 1) << 3;
    const int brow = tid >> 4, bcol = (tid & 15) << 3;

    const float* Ag = A + (size_t)(blockIdx.y * GBM + arow) * K + acol;
    const float* Bg = B + (size_t)brow * N + blockIdx.x * GBN + bcol;

    const uint32_t a_dst[2] = {
        (uint32_t)__cvta_generic_to_shared(&As[0][arow * APAD + acol]),
        (uint32_t)__cvta_generic_to_shared(&As[1][arow * APAD + acol]) };
    const uint32_t b_dst[2] = {
        (uint32_t)__cvta_generic_to_shared(&Bs[0][brow * BPAD + bcol]),
        (uint32_t)__cvta_generic_to_shared(&Bs[1][brow * BPAD + bcol]) };

    float acc[4][4][4];
    #pragma unroll
    for (int mf = 0; mf < 4; mf++)
        #pragma unroll
        for (int nf = 0; nf < 4; nf++)
            #pragma unroll
            for (int j = 0; j < 4; j++) acc[mf][nf][j] = 0.f;

    const int nIter = K / GBK;

    cp_async16(a_dst[0],      Ag);
    cp_async16(a_dst[0] + 16, Ag + 4);
    cp_async16(b_dst[0],      Bg);
    cp_async16(b_dst[0] + 16, Bg + 4);
    cp_async_commit();

    for (int it = 0; it < nIter; it++) {
        const int cur = it & 1, nxt = cur ^ 1;

        if (it + 1 < nIter) {
            const int k0 = (it + 1) * GBK;
            cp_async16(a_dst[nxt],      Ag + k0);
            cp_async16(a_dst[nxt] + 16, Ag + k0 + 4);
            cp_async16(b_dst[nxt],      Bg + (size_t)k0 * N);
            cp_async16(b_dst[nxt] + 16, Bg + (size_t)k0 * N + 4);
        }
        cp_async_commit();
        cp_async_wait1();
        __syncthreads();

        const float* Asc = As[cur];
        const float* Bsc = Bs[cur];

        #pragma unroll
        for (int kk = 0; kk < GBK; kk += 8) {
            uint32_t af[4][4], bf0[4], bf1[4];
            #pragma unroll
            for (int mf = 0; mf < 4; mf++) {
                const int r0 = wm * 64 + mf * 16 + g;
                af[mf][0] = f2tf(Asc[(r0    ) * APAD + kk + c    ]);
                af[mf][1] = f2tf(Asc[(r0 + 8) * APAD + kk + c    ]);
                af[mf][2] = f2tf(Asc[(r0    ) * APAD + kk + c + 4]);
                af[mf][3] = f2tf(Asc[(r0 + 8) * APAD + kk + c + 4]);
            }
            #pragma unroll
            for (int nf = 0; nf < 4; nf++) {
                const int n = wn * 32 + nf * 8 + g;
                bf0[nf] = f2tf(Bsc[(kk + c    ) * BPAD + n]);
                bf1[nf] = f2tf(Bsc[(kk + c + 4) * BPAD + n]);
            }
            #pragma unroll
            for (int mf = 0; mf < 4; mf++)
                #pragma unroll
                for (int nf = 0; nf < 4; nf++)
                    mma_tf32(acc[mf][nf], af[mf], bf0[nf], bf1[nf]);
        }
        __syncthreads();
    }

    #pragma unroll
    for (int mf = 0; mf < 4; mf++) {
        const int r0 = blockIdx.y * GBM + wm * 64 + mf * 16 + g;
        #pragma unroll
        for (int nf = 0; nf < 4; nf++) {
            const int col = blockIdx.x * GBN + wn * 32 + nf * 8 + 2 * c;
            float v0 = acc[mf][nf][0], v1 = acc[mf][nf][1];
            float v2 = acc[mf][nf][2], v3 = acc[mf][nf][3];
            if (cvt_out) {
                v0 = __uint_as_float(f2tf(v0)); v1 = __uint_as_float(f2tf(v1));
                v2 = __uint_as_float(f2tf(v2)); v3 = __uint_as_float(f2tf(v3));
            }
            *(float2*)&C[(size_t)r0 * N + col]       = make_float2(v0, v1);
            *(float2*)&C[(size_t)(r0 + 8) * N + col] = make_float2(v2, v3);
        }
    }
}

// ---------------------------------------------------------------------------
// TF32 flash attention, single-barrier double-buffered mainloop.
// Block = 256 threads (8 warps), 128 queries of one (b,h'); streams 64-key
// tiles. Per iteration: prefetch K(kt+1) to regs -> QK+softmax (hides K LDG)
// -> STS K -> prefetch V(kt+1) -> PV (hides V LDG) -> STS V -> ONE barrier.
// qkv holds pre-rounded tf32 bits -> staging is pure copy.
// ---------------------------------------------------------------------------
#define PAD 72
#define QT  128
#define KVT (64 * PAD)
#define OFF_K  (QT * PAD)                  /* 2 K buffers */
#define OFF_V  (OFF_K + 2 * KVT)           /* 2 V buffers */
#define OFF_MK (OFF_V + 2 * KVT)           /* 2 mask buffers (floats) */
#define ATT_SMEM_WORDS (OFF_MK + 2 * 64)
#define NTILES (SEQ / 64)

__global__ __launch_bounds__(256, 2)
void attn_mma_kernel(const uint32_t* __restrict__ qkv, const int* __restrict__ pmask,
                     float* __restrict__ attout) {
    extern __shared__ uint32_t smu[];
    uint32_t* Qs = smu;                     // [QT][PAD]; later reused as Ps
    uint32_t* Kb[2] = { smu + OFF_K, smu + OFF_K + KVT };
    uint32_t* Vb[2] = { smu + OFF_V, smu + OFF_V + KVT };
    float*    mkb[2] = { (float*)(smu + OFF_MK), (float*)(smu + OFF_MK) + 64 };

    const int qt = blockIdx.x, h = blockIdx.y, b = blockIdx.z;
    const int tid  = threadIdx.x;
    const int warp = tid >> 5;
    const int lane = tid & 31;
    const int g = lane >> 2;
    const int c = lane & 3;

    const size_t rbase = (size_t)b * (NHEAD * SEQ) + (size_t)h * SEQ;
    const uint32_t* qkv_b = qkv + rbase * (3 * HDIM);

    // Q loader: 2 thr/row (128 rows), 32 words each
    const int qrow  = tid >> 1;
    const int qhalf = (tid & 1) * 32;
    // KV loader: 4 thr/row (64 rows), 16 words each
    const int lrow = tid >> 2;
    const int lcol = (tid & 3) << 4;

    // ---- stage Q tile ----
    {
        const uint4* src = (const uint4*)(qkv_b + (size_t)(qt * QT + qrow) * (3 * HDIM) + qhalf);
        uint4* dst = (uint4*)&Qs[qrow * PAD + qhalf];
        #pragma unroll
        for (int u = 0; u < 8; u++) dst[u] = src[u];
    }
    // ---- stage K0, V0, mask0 directly ----
    {
        const uint4* srck = (const uint4*)(qkv_b + (size_t)lrow * (3 * HDIM) + HDIM + lcol);
        const uint4* srcv = (const uint4*)(qkv_b + (size_t)lrow * (3 * HDIM) + 2 * HDIM + lcol);
        uint4* dk = (uint4*)&Kb[0][lrow * PAD + lcol];
        uint4* dv = (uint4*)&Vb[0][lrow * PAD + lcol];
        #pragma unroll
        for (int u = 0; u < 4; u++) { dk[u] = srck[u]; dv[u] = srcv[u]; }
        if (tid < 64)
            mkb[0][tid] = (pmask[b * SEQ + tid] != 0) ? 0.f : -INFINITY;
    }
    __syncthreads();

    // ---- Q fragments ----
    uint32_t qa[8][4];
    {
        const int r0 = warp * 16 + g;
        #pragma unroll
        for (int ch = 0; ch < 8; ch++) {
            qa[ch][0] = Qs[(r0    ) * PAD + ch * 8 + c    ];
            qa[ch][1] = Qs[(r0 + 8) * PAD + ch * 8 + c    ];
            qa[ch][2] = Qs[(r0    ) * PAD + ch * 8 + c + 4];
            qa[ch][3] = Qs[(r0 + 8) * PAD + ch * 8 + c + 4];
        }
    }

    float o[8][4];
    #pragma unroll
    for (int nf = 0; nf < 8; nf++)
        #pragma unroll
        for (int j = 0; j < 4; j++) o[nf][j] = 0.f;
    float m0 = -INFINITY, m1 = -INFINITY, l0 = 0.f, l1 = 0.f;

    uint32_t* Ps = Qs;  // reuse after Q frags are in registers

    for (int kt = 0; kt < NTILES; kt++) {
        const int cur = kt & 1, nxt = cur ^ 1;
        const bool pf = (kt + 1 < NTILES);
        const uint32_t* Ks = Kb[cur];
        const uint32_t* Vs = Vb[cur];
        const float*    mk = mkb[cur];

        // ---- prefetch K(kt+1) into registers (latency hidden by QK+softmax) ----
        uint4 kr[4];
        int mreg = 0;
        if (pf) {
            const uint4* srck = (const uint4*)(qkv_b + (size_t)((kt + 1) * 64 + lrow) * (3 * HDIM) + HDIM + lcol);
            #pragma unroll
            for (int u = 0; u < 4; u++) kr[u] = srck[u];
            if (tid < 64) mreg = pmask[b * SEQ + (kt + 1) * 64 + tid];
        }

        // ---- S = Q K^T ----
        float s[8][4];
        #pragma unroll
        for (int kg = 0; kg < 8; kg++) {
            s[kg][0] = s[kg][1] = s[kg][2] = s[kg][3] = 0.f;
            const uint32_t* kbase = &Ks[(kg * 8 + g) * PAD + c];
            #pragma unroll
            for (int ch = 0; ch < 8; ch++)
                mma_tf32(s[kg], qa[ch], kbase[ch * 8], kbase[ch * 8 + 4]);
        }

        // ---- scale + mask ----
        #pragma unroll
        for (int kg = 0; kg < 8; kg++) {
            const int col0 = kg * 8 + 2 * c;
            float mk0 = mk[col0], mk1 = mk[col0 + 1];
            s[kg][0] = s[kg][0] * 0.125f + mk0;
            s[kg][1] = s[kg][1] * 0.125f + mk1;
            s[kg][2] = s[kg][2] * 0.125f + mk0;
            s[kg][3] = s[kg][3] * 0.125f + mk1;
        }

        // ---- online softmax ----
        float mx0 = -INFINITY, mx1 = -INFINITY;
        #pragma unroll
        for (int kg = 0; kg < 8; kg++) {
            mx0 = fmaxf(mx0, fmaxf(s[kg][0], s[kg][1]));
            mx1 = fmaxf(mx1, fmaxf(s[kg][2], s[kg][3]));
        }
        mx0 = fmaxf(mx0, __shfl_xor_sync(0xffffffffu, mx0, 1));
        mx0 = fmaxf(mx0, __shfl_xor_sync(0xffffffffu, mx0, 2));
        mx1 = fmaxf(mx1, __shfl_xor_sync(0xffffffffu, mx1, 1));
        mx1 = fmaxf(mx1, __shfl_xor_sync(0xffffffffu, mx1, 2));

        float mn0 = fmaxf(m0, mx0), mn1 = fmaxf(m1, mx1);
        float sc0 = (mn0 == -INFINITY) ? 1.f : __expf(m0 - mn0);
        float sc1 = (mn1 == -INFINITY) ? 1.f : __expf(m1 - mn1);

        float sum0 = 0.f, sum1 = 0.f;
        {
            const int r0 = warp * 16 + g;
            uint32_t* pdst0 = &Ps[(r0    ) * PAD + 2 * c];
            uint32_t* pdst1 = &Ps[(r0 + 8) * PAD + 2 * c];
            #pragma unroll
            for (int kg = 0; kg < 8; kg++) {
                float p0 = (s[kg][0] == -INFINITY) ? 0.f : __expf(s[kg][0] - mn0);
                float p1 = (s[kg][1] == -INFINITY) ? 0.f : __expf(s[kg][1] - mn0);
                float p2 = (s[kg][2] == -INFINITY) ? 0.f : __expf(s[kg][2] - mn1);
                float p3 = (s[kg][3] == -INFINITY) ? 0.f : __expf(s[kg][3] - mn1);
                uint32_t t0 = f2tf(p0), t1 = f2tf(p1), t2 = f2tf(p2), t3 = f2tf(p3);
                sum0 += __uint_as_float(t0) + __uint_as_float(t1);
                sum1 += __uint_as_float(t2) + __uint_as_float(t3);
                *(uint2*)(pdst0 + kg * 8) = make_uint2(t0, t1);
                *(uint2*)(pdst1 + kg * 8) = make_uint2(t2, t3);
            }
        }
        sum0 += __shfl_xor_sync(0xffffffffu, sum0, 1);
        sum0 += __shfl_xor_sync(0xffffffffu, sum0, 2);
        sum1 += __shfl_xor_sync(0xffffffffu, sum1, 1);
        sum1 += __shfl_xor_sync(0xffffffffu, sum1, 2);

        l0 = l0 * sc0 + sum0;  m0 = mn0;
        l1 = l1 * sc1 + sum1;  m1 = mn1;

        #pragma unroll
        for (int nf = 0; nf < 8; nf++) {
            o[nf][0] *= sc0; o[nf][1] *= sc0;
            o[nf][2] *= sc1; o[nf][3] *= sc1;
        }

        // ---- store prefetched K into next buffer; retire K regs ----
        if (pf) {
            uint4* dk = (uint4*)&Kb[nxt][lrow * PAD + lcol];
            #pragma unroll
            for (int u = 0; u < 4; u++) dk[u] = kr[u];
            if (tid < 64) mkb[nxt][tid] = (mreg != 0) ? 0.f : -INFINITY;
        }
        __syncwarp();   // Ps rows are warp-private

        // ---- prefetch V(kt+1) into registers (latency hidden by PV) ----
        uint4 vr[4];
        if (pf) {
            const uint4* srcv = (const uint4*)(qkv_b + (size_t)((kt + 1) * 64 + lrow) * (3 * HDIM) + 2 * HDIM + lcol);
            #pragma unroll
            for (int u = 0; u < 4; u++) vr[u] = srcv[u];
        }

        // ---- O += P V ----
        #pragma unroll
        for (int ch = 0; ch < 8; ch++) {
            uint32_t pa[4];
            const int r0 = warp * 16 + g;
            pa[0] = Ps[(r0    ) * PAD + ch * 8 + c    ];
            pa[1] = Ps[(r0 + 8) * PAD + ch * 8 + c    ];
            pa[2] = Ps[(r0    ) * PAD + ch * 8 + c + 4];
            pa[3] = Ps[(r0 + 8) * PAD + ch * 8 + c + 4];
            const uint32_t* vb0 = &Vs[(ch * 8 + c    ) * PAD + g];
            const uint32_t* vb1 = &Vs[(ch * 8 + c + 4) * PAD + g];
            #pragma unroll
            for (int nf = 0; nf < 8; nf++)
                mma_tf32(o[nf], pa, vb0[nf * 8], vb1[nf * 8]);
        }

        // ---- store prefetched V into next buffer; single barrier ----
        if (pf) {
            uint4* dv = (uint4*)&Vb[nxt][lrow * PAD + lcol];
            #pragma unroll
            for (int u = 0; u < 4; u++) dv[u] = vr[u];
        }
        __syncthreads();
    }

    // ---- epilogue ----
    {
        const int r0 = warp * 16 + g;
        const int row0 = qt * QT + r0, row1 = row0 + 8;
        float inv0 = (l0 > 0.f) ? (1.f / l0) : 0.f;
        float inv1 = (l1 > 0.f) ? (1.f / l1) : 0.f;
        if (pmask[b * SEQ + row0] == 0) inv0 = 0.f;
        if (pmask[b * SEQ + row1] == 0) inv1 = 0.f;
        float* out0 = attout + (rbase + row0) * HDIM + 2 * c;
        float* out1 = attout + (rbase + row1) * HDIM + 2 * c;
        #pragma unroll
        for (int nf = 0; nf < 8; nf++) {
            *(float2*)(out0 + nf * 8) = make_float2(o[nf][0] * inv0, o[nf][1] * inv0);
            *(float2*)(out1 + nf * 8) = make_float2(o[nf][2] * inv1, o[nf][3] * inv1);
        }
    }
}

// ---------------------------------------------------------------------------
extern "C" void kernel_launch(void* const* d_in, const int* in_sizes, int n_in,
                              void* d_out, int out_size) {
    const float* x     = (const float*)d_in[0];
    const int*   pmask = (const int*)d_in[2];
    const float* Wqkv  = (const float*)d_in[3];
    const float* Wout  = (const float*)d_in[4];
    float* out = (float*)d_out;

    float *qkv_p = nullptr, *att_p = nullptr;
    cudaGetSymbolAddress((void**)&qkv_p, g_qkv);
    cudaGetSymbolAddress((void**)&att_p, g_att);

    const int attn_smem = ATT_SMEM_WORDS * (int)sizeof(uint32_t);
    cudaFuncSetAttribute(attn_mma_kernel, cudaFuncAttributeMaxDynamicSharedMemorySize, attn_smem);

    // 1) QKV = x @ W_qkv : [8192,512] @ [512,1536]  (output tf32-rounded bits)
    tf32_gemm_kernel<<<dim3(QKVN / GBN, ROWS / GBM), 256>>>(x, Wqkv, qkv_p, ROWS, QKVN, DMODEL, 1);

    // 2) tf32 tensor-core attention over the reshaped (flat) layout
    attn_mma_kernel<<<dim3(SEQ / QT, NHEAD, BATCH), 256, attn_smem>>>(
        (const uint32_t*)qkv_p, pmask, att_p);

    // 3) out = att @ W_out : [8192,512] @ [512,512]  (plain fp32 output)
    tf32_gemm_kernel<<<dim3(DMODEL / GBN, ROWS / GBM), 256>>>(att_p, Wout, out, ROWS, DMODEL, DMODEL, 0);
}

// round 11
// speedup vs baseline: 1.1072x; 1.1072x over previous
#include <cuda_runtime.h>
#include <math.h>
#include <stdint.h>

#define BATCH   4
#define SEQ     2048
#define DMODEL  512
#define NHEAD   8
#define HDIM    64
#define ROWS    (BATCH * SEQ)        /* 8192 */
#define QKVN    (3 * DMODEL)         /* 1536 */

// Scratch (allocation-free rule: device globals). All tf32-bit buffers.
__device__ uint32_t g_qkv[(size_t)ROWS * QKVN];     // [8192, 1536] tf32 bits
__device__ uint32_t g_att[(size_t)ROWS * DMODEL];   // [8192, 512]  tf32 bits
__device__ uint32_t g_x  [(size_t)ROWS * DMODEL];   // x rounded
__device__ uint32_t g_wq [(size_t)DMODEL * QKVN];   // W_qkv rounded
__device__ uint32_t g_wo [(size_t)DMODEL * DMODEL]; // W_out rounded

__device__ __forceinline__ uint32_t f2tf(float x) {
    uint32_t r;
    asm("cvt.rna.tf32.f32 %0, %1;" : "=r"(r) : "f"(x));
    return r;
}

__device__ __forceinline__ void mma_tf32(float c[4], const uint32_t a[4],
                                         uint32_t b0, uint32_t b1) {
    asm volatile(
        "mma.sync.aligned.m16n8k8.row.col.f32.tf32.tf32.f32 "
        "{%0,%1,%2,%3}, {%4,%5,%6,%7}, {%8,%9}, {%0,%1,%2,%3};"
        : "+f"(c[0]), "+f"(c[1]), "+f"(c[2]), "+f"(c[3])
        : "r"(a[0]), "r"(a[1]), "r"(a[2]), "r"(a[3]), "r"(b0), "r"(b1));
}

__device__ __forceinline__ void cp_async16(uint32_t smem_dst, const void* gsrc) {
    asm volatile("cp.async.cg.shared.global [%0], [%1], 16;"
                 :: "r"(smem_dst), "l"(gsrc) : "memory");
}
__device__ __forceinline__ void cp_async_commit() {
    asm volatile("cp.async.commit_group;" ::: "memory");
}
__device__ __forceinline__ void cp_async_wait1() {
    asm volatile("cp.async.wait_group 1;" ::: "memory");
}

// ---------------------------------------------------------------------------
// One-shot tf32 rounding pass: x, W_qkv, W_out -> tf32-bit scratch buffers.
// f2tf is idempotent, so downstream results are bit-identical to rounding
// at fragment-load time.
// ---------------------------------------------------------------------------
#define N1 ((ROWS * DMODEL) / 4)
#define N2 ((DMODEL * QKVN) / 4)
#define N3 ((DMODEL * DMODEL) / 4)

__global__ __launch_bounds__(256)
void round_tf32_kernel(const float4* __restrict__ x, const float4* __restrict__ wq,
                       const float4* __restrict__ wo) {
    const int stride = gridDim.x * blockDim.x;
    for (int i = blockIdx.x * blockDim.x + threadIdx.x; i < N1 + N2 + N3; i += stride) {
        float4 v; uint4* dst;
        if (i < N1)            { v = x[i];            dst = (uint4*)g_x  + i;        }
        else if (i < N1 + N2)  { v = wq[i - N1];      dst = (uint4*)g_wq + (i - N1); }
        else                   { v = wo[i - N1 - N2]; dst = (uint4*)g_wo + (i - N1 - N2); }
        *dst = make_uint4(f2tf(v.x), f2tf(v.y), f2tf(v.z), f2tf(v.w));
    }
}

// ---------------------------------------------------------------------------
// TF32 tensor-core GEMM, 2-stage cp.async pipeline. Operands are PRE-ROUNDED
// tf32 bits -> fragment loads are pure LDS (no cvt in the mainloop).
// C[M,N] = A[M,K] @ B[K,N]. 128x128x16 block tile, 8 warps, 64x32 warp tile.
// cvt_out != 0: C stored as tf32-rounded bits; else plain fp32.
// ---------------------------------------------------------------------------
#define GBM 128
#define GBN 128
#define GBK 16
#define APAD 20
#define BPAD 136
#define AW (GBM * APAD)
#define BW (GBK * BPAD)

__global__ __launch_bounds__(256)
void tf32_gemm_kernel(const uint32_t* __restrict__ A, const uint32_t* __restrict__ B,
                      float* __restrict__ C, int M, int N, int K, int cvt_out) {
    __shared__ uint32_t As[2][AW];
    __shared__ uint32_t Bs[2][BW];

    const int tid  = threadIdx.x;
    const int warp = tid >> 5;
    const int lane = tid & 31;
    const int g = lane >> 2;
    const int c = lane & 3;
    const int wm = warp >> 2;
    const int wn = warp & 3;

    const int arow = tid >> 1, acol = (tid & 1) << 3;
    const int brow = tid >> 4, bcol = (tid & 15) << 3;

    const uint32_t* Ag = A + (size_t)(blockIdx.y * GBM + arow) * K + acol;
    const uint32_t* Bg = B + (size_t)brow * N + blockIdx.x * GBN + bcol;

    const uint32_t a_dst[2] = {
        (uint32_t)__cvta_generic_to_shared(&As[0][arow * APAD + acol]),
        (uint32_t)__cvta_generic_to_shared(&As[1][arow * APAD + acol]) };
    const uint32_t b_dst[2] = {
        (uint32_t)__cvta_generic_to_shared(&Bs[0][brow * BPAD + bcol]),
        (uint32_t)__cvta_generic_to_shared(&Bs[1][brow * BPAD + bcol]) };

    float acc[4][4][4];
    #pragma unroll
    for (int mf = 0; mf < 4; mf++)
        #pragma unroll
        for (int nf = 0; nf < 4; nf++)
            #pragma unroll
            for (int j = 0; j < 4; j++) acc[mf][nf][j] = 0.f;

    const int nIter = K / GBK;

    cp_async16(a_dst[0],      Ag);
    cp_async16(a_dst[0] + 16, Ag + 4);
    cp_async16(b_dst[0],      Bg);
    cp_async16(b_dst[0] + 16, Bg + 4);
    cp_async_commit();

    for (int it = 0; it < nIter; it++) {
        const int cur = it & 1, nxt = cur ^ 1;

        if (it + 1 < nIter) {
            const int k0 = (it + 1) * GBK;
            cp_async16(a_dst[nxt],      Ag + k0);
            cp_async16(a_dst[nxt] + 16, Ag + k0 + 4);
            cp_async16(b_dst[nxt],      Bg + (size_t)k0 * N);
            cp_async16(b_dst[nxt] + 16, Bg + (size_t)k0 * N + 4);
        }
        cp_async_commit();
        cp_async_wait1();
        __syncthreads();

        const uint32_t* Asc = As[cur];
        const uint32_t* Bsc = Bs[cur];

        #pragma unroll
        for (int kk = 0; kk < GBK; kk += 8) {
            uint32_t af[4][4], bf0[4], bf1[4];
            #pragma unroll
            for (int mf = 0; mf < 4; mf++) {
                const int r0 = wm * 64 + mf * 16 + g;
                af[mf][0] = Asc[(r0    ) * APAD + kk + c    ];
                af[mf][1] = Asc[(r0 + 8) * APAD + kk + c    ];
                af[mf][2] = Asc[(r0    ) * APAD + kk + c + 4];
                af[mf][3] = Asc[(r0 + 8) * APAD + kk + c + 4];
            }
            #pragma unroll
            for (int nf = 0; nf < 4; nf++) {
                const int n = wn * 32 + nf * 8 + g;
                bf0[nf] = Bsc[(kk + c    ) * BPAD + n];
                bf1[nf] = Bsc[(kk + c + 4) * BPAD + n];
            }
            #pragma unroll
            for (int mf = 0; mf < 4; mf++)
                #pragma unroll
                for (int nf = 0; nf < 4; nf++)
                    mma_tf32(acc[mf][nf], af[mf], bf0[nf], bf1[nf]);
        }
        __syncthreads();
    }

    #pragma unroll
    for (int mf = 0; mf < 4; mf++) {
        const int r0 = blockIdx.y * GBM + wm * 64 + mf * 16 + g;
        #pragma unroll
        for (int nf = 0; nf < 4; nf++) {
            const int col = blockIdx.x * GBN + wn * 32 + nf * 8 + 2 * c;
            if (cvt_out) {
                uint32_t* Cu = (uint32_t*)C;
                *(uint2*)&Cu[(size_t)r0 * N + col] =
                    make_uint2(f2tf(acc[mf][nf][0]), f2tf(acc[mf][nf][1]));
                *(uint2*)&Cu[(size_t)(r0 + 8) * N + col] =
                    make_uint2(f2tf(acc[mf][nf][2]), f2tf(acc[mf][nf][3]));
            } else {
                *(float2*)&C[(size_t)r0 * N + col] =
                    make_float2(acc[mf][nf][0], acc[mf][nf][1]);
                *(float2*)&C[(size_t)(r0 + 8) * N + col] =
                    make_float2(acc[mf][nf][2], acc[mf][nf][3]);
            }
        }
    }
}

// ---------------------------------------------------------------------------
// TF32 tensor-core flash attention (exact 588us config; only the epilogue
// now stores tf32-rounded bits, which GEMM3 would have produced anyway).
// Block = 256 threads (8 warps), 128 queries of one (b,h'); streams 64-key
// tiles. qkv holds pre-rounded tf32 bits -> staging is pure copy.
// ---------------------------------------------------------------------------
#define PAD 72
#define QT  128
#define ATT_SMEM_WORDS (QT * PAD + 2 * 64 * PAD + 64)

__global__ __launch_bounds__(256)
void attn_mma_kernel(const uint32_t* __restrict__ qkv, const int* __restrict__ pmask,
                     uint32_t* __restrict__ attout) {
    extern __shared__ uint32_t smu[];
    uint32_t* Qs = smu;                  // [QT][PAD]; later reused as Ps
    uint32_t* Ks = Qs + QT * PAD;        // [64][PAD]
    uint32_t* Vs = Ks + 64 * PAD;        // [64][PAD]
    float*    mk = (float*)(Vs + 64 * PAD);  // [64]

    const int qt = blockIdx.x, h = blockIdx.y, b = blockIdx.z;
    const int tid  = threadIdx.x;
    const int warp = tid >> 5;
    const int lane = tid & 31;
    const int g = lane >> 2;
    const int c = lane & 3;

    const size_t rbase = (size_t)b * (NHEAD * SEQ) + (size_t)h * SEQ;
    const uint32_t* qkv_b = qkv + rbase * (3 * HDIM);

    const int qrow  = tid >> 1;
    const int qhalf = (tid & 1) * 32;
    const int lrow = tid >> 2;
    const int lcol = (tid & 3) << 4;

    // ---- stage Q tile (pure copy, already tf32) ----
    {
        const uint4* src = (const uint4*)(qkv_b + (size_t)(qt * QT + qrow) * (3 * HDIM) + qhalf);
        uint4* dst = (uint4*)&Qs[qrow * PAD + qhalf];
        #pragma unroll
        for (int u = 0; u < 8; u++) dst[u] = src[u];
    }
    __syncthreads();

    // ---- Q fragments ----
    uint32_t qa[8][4];
    {
        const int r0 = warp * 16 + g;
        #pragma unroll
        for (int ch = 0; ch < 8; ch++) {
            qa[ch][0] = Qs[(r0    ) * PAD + ch * 8 + c    ];
            qa[ch][1] = Qs[(r0 + 8) * PAD + ch * 8 + c    ];
            qa[ch][2] = Qs[(r0    ) * PAD + ch * 8 + c + 4];
            qa[ch][3] = Qs[(r0 + 8) * PAD + ch * 8 + c + 4];
        }
    }

    float o[8][4];
    #pragma unroll
    for (int nf = 0; nf < 8; nf++)
        #pragma unroll
        for (int j = 0; j < 4; j++) o[nf][j] = 0.f;
    float m0 = -INFINITY, m1 = -INFINITY, l0 = 0.f, l1 = 0.f;

    uint32_t* Ps = Qs;  // reuse after Q frags are in registers

    for (int kt = 0; kt < SEQ / 64; kt++) {
        __syncthreads();   // prior-iteration reads of Ks/Vs/mk complete

        // ---- stage K, V tiles (pure copy) + mask ----
        {
            const uint4* srck = (const uint4*)(qkv_b + (size_t)(kt * 64 + lrow) * (3 * HDIM) + HDIM + lcol);
            const uint4* srcv = (const uint4*)(qkv_b + (size_t)(kt * 64 + lrow) * (3 * HDIM) + 2 * HDIM + lcol);
            uint4* dk = (uint4*)&Ks[lrow * PAD + lcol];
            uint4* dv = (uint4*)&Vs[lrow * PAD + lcol];
            #pragma unroll
            for (int u = 0; u < 4; u++) { dk[u] = srck[u]; dv[u] = srcv[u]; }
            if (tid < 64)
                mk[tid] = (pmask[b * SEQ + kt * 64 + tid] != 0) ? 0.f : -INFINITY;
        }
        __syncthreads();

        // ---- S = Q K^T ----
        float s[8][4];
        #pragma unroll
        for (int kg = 0; kg < 8; kg++) {
            s[kg][0] = s[kg][1] = s[kg][2] = s[kg][3] = 0.f;
            const uint32_t* kbase = &Ks[(kg * 8 + g) * PAD + c];
            #pragma unroll
            for (int ch = 0; ch < 8; ch++)
                mma_tf32(s[kg], qa[ch], kbase[ch * 8], kbase[ch * 8 + 4]);
        }

        // ---- scale + mask ----
        #pragma unroll
        for (int kg = 0; kg < 8; kg++) {
            const int col0 = kg * 8 + 2 * c;
            float mk0 = mk[col0], mk1 = mk[col0 + 1];
            s[kg][0] = s[kg][0] * 0.125f + mk0;
            s[kg][1] = s[kg][1] * 0.125f + mk1;
            s[kg][2] = s[kg][2] * 0.125f + mk0;
            s[kg][3] = s[kg][3] * 0.125f + mk1;
        }

        // ---- online softmax ----
        float mx0 = -INFINITY, mx1 = -INFINITY;
        #pragma unroll
        for (int kg = 0; kg < 8; kg++) {
            mx0 = fmaxf(mx0, fmaxf(s[kg][0], s[kg][1]));
            mx1 = fmaxf(mx1, fmaxf(s[kg][2], s[kg][3]));
        }
        mx0 = fmaxf(mx0, __shfl_xor_sync(0xffffffffu, mx0, 1));
        mx0 = fmaxf(mx0, __shfl_xor_sync(0xffffffffu, mx0, 2));
        mx1 = fmaxf(mx1, __shfl_xor_sync(0xffffffffu, mx1, 1));
        mx1 = fmaxf(mx1, __shfl_xor_sync(0xffffffffu, mx1, 2));

        float mn0 = fmaxf(m0, mx0), mn1 = fmaxf(m1, mx1);
        float sc0 = (mn0 == -INFINITY) ? 1.f : __expf(m0 - mn0);
        float sc1 = (mn1 == -INFINITY) ? 1.f : __expf(m1 - mn1);

        float sum0 = 0.f, sum1 = 0.f;
        {
            const int r0 = warp * 16 + g;
            uint32_t* pdst0 = &Ps[(r0    ) * PAD + 2 * c];
            uint32_t* pdst1 = &Ps[(r0 + 8) * PAD + 2 * c];
            #pragma unroll
            for (int kg = 0; kg < 8; kg++) {
                float p0 = (s[kg][0] == -INFINITY) ? 0.f : __expf(s[kg][0] - mn0);
                float p1 = (s[kg][1] == -INFINITY) ? 0.f : __expf(s[kg][1] - mn0);
                float p2 = (s[kg][2] == -INFINITY) ? 0.f : __expf(s[kg][2] - mn1);
                float p3 = (s[kg][3] == -INFINITY) ? 0.f : __expf(s[kg][3] - mn1);
                uint32_t t0 = f2tf(p0), t1 = f2tf(p1), t2 = f2tf(p2), t3 = f2tf(p3);
                sum0 += __uint_as_float(t0) + __uint_as_float(t1);
                sum1 += __uint_as_float(t2) + __uint_as_float(t3);
                *(uint2*)(pdst0 + kg * 8) = make_uint2(t0, t1);
                *(uint2*)(pdst1 + kg * 8) = make_uint2(t2, t3);
            }
        }
        sum0 += __shfl_xor_sync(0xffffffffu, sum0, 1);
        sum0 += __shfl_xor_sync(0xffffffffu, sum0, 2);
        sum1 += __shfl_xor_sync(0xffffffffu, sum1, 1);
        sum1 += __shfl_xor_sync(0xffffffffu, sum1, 2);

        l0 = l0 * sc0 + sum0;  m0 = mn0;
        l1 = l1 * sc1 + sum1;  m1 = mn1;

        #pragma unroll
        for (int nf = 0; nf < 8; nf++) {
            o[nf][0] *= sc0; o[nf][1] *= sc0;
            o[nf][2] *= sc1; o[nf][3] *= sc1;
        }
        __syncwarp();   // Ps rows are warp-private

        // ---- O += P V ----
        #pragma unroll
        for (int ch = 0; ch < 8; ch++) {
            uint32_t pa[4];
            const int r0 = warp * 16 + g;
            pa[0] = Ps[(r0    ) * PAD + ch * 8 + c    ];
            pa[1] = Ps[(r0 + 8) * PAD + ch * 8 + c    ];
            pa[2] = Ps[(r0    ) * PAD + ch * 8 + c + 4];
            pa[3] = Ps[(r0 + 8) * PAD + ch * 8 + c + 4];
            const uint32_t* vb0 = &Vs[(ch * 8 + c    ) * PAD + g];
            const uint32_t* vb1 = &Vs[(ch * 8 + c + 4) * PAD + g];
            #pragma unroll
            for (int nf = 0; nf < 8; nf++)
                mma_tf32(o[nf], pa, vb0[nf * 8], vb1[nf * 8]);
        }
        __syncwarp();
    }

    // ---- epilogue: normalize, validity, store tf32-rounded bits ----
    {
        const int r0 = warp * 16 + g;
        const int row0 = qt * QT + r0, row1 = row0 + 8;
        float inv0 = (l0 > 0.f) ? (1.f / l0) : 0.f;
        float inv1 = (l1 > 0.f) ? (1.f / l1) : 0.f;
        if (pmask[b * SEQ + row0] == 0) inv0 = 0.f;
        if (pmask[b * SEQ + row1] == 0) inv1 = 0.f;
        uint32_t* out0 = attout + (rbase + row0) * HDIM + 2 * c;
        uint32_t* out1 = attout + (rbase + row1) * HDIM + 2 * c;
        #pragma unroll
        for (int nf = 0; nf < 8; nf++) {
            *(uint2*)(out0 + nf * 8) = make_uint2(f2tf(o[nf][0] * inv0), f2tf(o[nf][1] * inv0));
            *(uint2*)(out1 + nf * 8) = make_uint2(f2tf(o[nf][2] * inv1), f2tf(o[nf][3] * inv1));
        }
    }
}

// ---------------------------------------------------------------------------
extern "C" void kernel_launch(void* const* d_in, const int* in_sizes, int n_in,
                              void* d_out, int out_size) {
    const float* x     = (const float*)d_in[0];
    const int*   pmask = (const int*)d_in[2];
    const float* Wqkv  = (const float*)d_in[3];
    const float* Wout  = (const float*)d_in[4];
    float* out = (float*)d_out;

    uint32_t *qkv_p, *att_p, *x_p, *wq_p, *wo_p;
    cudaGetSymbolAddress((void**)&qkv_p, g_qkv);
    cudaGetSymbolAddress((void**)&att_p, g_att);
    cudaGetSymbolAddress((void**)&x_p,   g_x);
    cudaGetSymbolAddress((void**)&wq_p,  g_wq);
    cudaGetSymbolAddress((void**)&wo_p,  g_wo);

    const int attn_smem = ATT_SMEM_WORDS * (int)sizeof(uint32_t);
    cudaFuncSetAttribute(attn_mma_kernel, cudaFuncAttributeMaxDynamicSharedMemorySize, attn_smem);

    // 0) pre-round all GEMM inputs to tf32 bits (idempotent -> bit-identical)
    round_tf32_kernel<<<1184, 256>>>((const float4*)x, (const float4*)Wqkv, (const float4*)Wout);

    // 1) QKV = x @ W_qkv : [8192,512] @ [512,1536]  (output tf32 bits)
    tf32_gemm_kernel<<<dim3(QKVN / GBN, ROWS / GBM), 256>>>(x_p, wq_p, (float*)qkv_p, ROWS, QKVN, DMODEL, 1);

    // 2) tf32 tensor-core attention over the reshaped (flat) layout
    attn_mma_kernel<<<dim3(SEQ / QT, NHEAD, BATCH), 256, attn_smem>>>(qkv_p, pmask, att_p);

    // 3) out = att @ W_out : [8192,512] @ [512,512]  (plain fp32 output)
    tf32_gemm_kernel<<<dim3(DMODEL / GBN, ROWS / GBM), 256>>>(att_p, wo_p, out, ROWS, DMODEL, DMODEL, 0);
}